// round 1
// baseline (speedup 1.0000x reference)
#include <cuda_runtime.h>

// Problem constants
#define BB  8
#define NN_ 2048
#define DD  128
#define NH  8
#define NL  4
#define SPLITK 16   // gram split-K: 16 chunks of 128 rows -> 128 blocks
#define KT  16      // k-tile for all GEMMs

// Scratch (device globals: no allocation allowed in kernel_launch)
__device__ float g_G[BB * DD * DD];        // per-batch Gram  Z^T Z      (512 KB)
__device__ float g_T[BB * NH * DD * DD];   // per-(b,head)   Q_j @ G_b   (4 MB)
__device__ float g_M[BB * DD * DD];        // per-batch      sum_j T V^T (512 KB)

// ---------------------------------------------------------------------------
__global__ void zero_kernel() {
    int i = blockIdx.x * blockDim.x + threadIdx.x;
    if (i < BB * DD * DD) { g_G[i] = 0.0f; g_M[i] = 0.0f; }
}

// ---------------------------------------------------------------------------
// G[b] += Zchunk^T @ Zchunk, chunk = 128 rows. grid (SPLITK, B), 256 thr.
// Output tile 128x128, per-thread 8x8.
__global__ __launch_bounds__(256) void gram_kernel(const float* __restrict__ Z) {
    const int b = blockIdx.y, s = blockIdx.x;
    const float* Zb = Z + ((size_t)b * NN_ + (size_t)s * (NN_ / SPLITK)) * DD;
    __shared__ float Zs[KT][DD];

    const int tid = threadIdx.x;
    const int tx = tid & 15, ty = tid >> 4;

    float acc[8][8];
#pragma unroll
    for (int u = 0; u < 8; u++)
#pragma unroll
        for (int v = 0; v < 8; v++) acc[u][v] = 0.0f;

    for (int k0 = 0; k0 < NN_ / SPLITK; k0 += KT) {
        // KT x 128 = 2048 floats, contiguous in gmem
        const float4* src = (const float4*)(Zb + (size_t)k0 * DD);
        float4* dst = (float4*)&Zs[0][0];
        dst[tid]       = src[tid];
        dst[tid + 256] = src[tid + 256];
        __syncthreads();

#pragma unroll
        for (int k = 0; k < KT; k++) {
            float a[8], bv[8];
            *(float4*)&a[0]  = *(const float4*)&Zs[k][ty * 8];
            *(float4*)&a[4]  = *(const float4*)&Zs[k][ty * 8 + 4];
            *(float4*)&bv[0] = *(const float4*)&Zs[k][tx * 8];
            *(float4*)&bv[4] = *(const float4*)&Zs[k][tx * 8 + 4];
#pragma unroll
            for (int u = 0; u < 8; u++)
#pragma unroll
                for (int v = 0; v < 8; v++)
                    acc[u][v] = fmaf(a[u], bv[v], acc[u][v]);
        }
        __syncthreads();
    }

    float* Gb = g_G + (size_t)b * DD * DD;
#pragma unroll
    for (int u = 0; u < 8; u++)
#pragma unroll
        for (int v = 0; v < 8; v++)
            atomicAdd(&Gb[(size_t)(ty * 8 + u) * DD + tx * 8 + v], acc[u][v]);
}

// ---------------------------------------------------------------------------
// T[b,j] = Q_j @ G_b.  grid (2,2,B*NH): 64x64 tile, 256 thr, 4x4/thread.
__global__ __launch_bounds__(256) void qg_kernel(const float* __restrict__ Qm) {
    const int bj = blockIdx.z;
    const int j  = bj & 7;
    const float* A  = Qm + (size_t)j * DD * DD;            // Q_j  [i][k]
    const float* Bm = g_G + (size_t)(bj >> 3) * DD * DD;   // G_b  [k][jj]
    float* Cm = g_T + (size_t)bj * DD * DD;

    const int i0 = blockIdx.y * 64, jj0 = blockIdx.x * 64;
    const int tid = threadIdx.x;
    const int tx = tid & 15, ty = tid >> 4;

    __shared__ float As[KT][64], Bs[KT][64];
    float acc[4][4];
#pragma unroll
    for (int u = 0; u < 4; u++)
#pragma unroll
        for (int v = 0; v < 4; v++) acc[u][v] = 0.0f;

    for (int k0 = 0; k0 < DD; k0 += KT) {
        {   // A transposed into smem: As[kk][i] = A[i0+i][k0+kk]
            int r = tid >> 2, c4 = (tid & 3) * 4;
            float4 v = *(const float4*)&A[(size_t)(i0 + r) * DD + k0 + c4];
            As[c4 + 0][r] = v.x; As[c4 + 1][r] = v.y;
            As[c4 + 2][r] = v.z; As[c4 + 3][r] = v.w;
        }
        {   // B direct: Bs[kk][jj] = Bm[k0+kk][jj0+jj]
            int r = tid >> 4, c = (tid & 15) * 4;
            *(float4*)&Bs[r][c] = *(const float4*)&Bm[(size_t)(k0 + r) * DD + jj0 + c];
        }
        __syncthreads();
#pragma unroll
        for (int k = 0; k < KT; k++) {
            float a[4], bv[4];
            *(float4*)&a[0]  = *(const float4*)&As[k][ty * 4];
            *(float4*)&bv[0] = *(const float4*)&Bs[k][tx * 4];
#pragma unroll
            for (int u = 0; u < 4; u++)
#pragma unroll
                for (int v = 0; v < 4; v++)
                    acc[u][v] = fmaf(a[u], bv[v], acc[u][v]);
        }
        __syncthreads();
    }
#pragma unroll
    for (int u = 0; u < 4; u++) {
        float4 o = make_float4(acc[u][0], acc[u][1], acc[u][2], acc[u][3]);
        *(float4*)&Cm[(size_t)(i0 + ty * 4 + u) * DD + jj0 + tx * 4] = o;
    }
}

// ---------------------------------------------------------------------------
// M[b] += (1/(N*NH)) * T[b,j] @ V_j^T.  grid (2,2,B*NH).
__global__ __launch_bounds__(256) void tv_kernel(const float* __restrict__ Vm) {
    const int bj = blockIdx.z;
    const int j  = bj & 7;
    const int b  = bj >> 3;
    const float* A  = g_T + (size_t)bj * DD * DD;   // T [i][k]
    const float* Vj = Vm + (size_t)j * DD * DD;     // V [jj][k] -> B^T
    float* Mb = g_M + (size_t)b * DD * DD;

    const int i0 = blockIdx.y * 64, jj0 = blockIdx.x * 64;
    const int tid = threadIdx.x;
    const int tx = tid & 15, ty = tid >> 4;

    __shared__ float As[KT][64], Bs[KT][64];
    float acc[4][4];
#pragma unroll
    for (int u = 0; u < 4; u++)
#pragma unroll
        for (int v = 0; v < 4; v++) acc[u][v] = 0.0f;

    for (int k0 = 0; k0 < DD; k0 += KT) {
        {   // As[kk][i] = A[i0+i][k0+kk]
            int r = tid >> 2, c4 = (tid & 3) * 4;
            float4 v = *(const float4*)&A[(size_t)(i0 + r) * DD + k0 + c4];
            As[c4 + 0][r] = v.x; As[c4 + 1][r] = v.y;
            As[c4 + 2][r] = v.z; As[c4 + 3][r] = v.w;
        }
        {   // Bs[kk][jj] = V[jj0+jj][k0+kk]   (transpose load)
            int r = tid >> 2, c4 = (tid & 3) * 4;
            float4 v = *(const float4*)&Vj[(size_t)(jj0 + r) * DD + k0 + c4];
            Bs[c4 + 0][r] = v.x; Bs[c4 + 1][r] = v.y;
            Bs[c4 + 2][r] = v.z; Bs[c4 + 3][r] = v.w;
        }
        __syncthreads();
#pragma unroll
        for (int k = 0; k < KT; k++) {
            float a[4], bv[4];
            *(float4*)&a[0]  = *(const float4*)&As[k][ty * 4];
            *(float4*)&bv[0] = *(const float4*)&Bs[k][tx * 4];
#pragma unroll
            for (int u = 0; u < 4; u++)
#pragma unroll
                for (int v = 0; v < 4; v++)
                    acc[u][v] = fmaf(a[u], bv[v], acc[u][v]);
        }
        __syncthreads();
    }
    const float scale = 1.0f / ((float)NN_ * (float)NH);
#pragma unroll
    for (int u = 0; u < 4; u++)
#pragma unroll
        for (int v = 0; v < 4; v++)
            atomicAdd(&Mb[(size_t)(i0 + ty * 4 + u) * DD + jj0 + tx * 4 + v],
                      acc[u][v] * scale);
}

// ---------------------------------------------------------------------------
// Zout = Zin + Zin @ M[b].  Row-local -> in-place safe.
// grid (N/128, B), 128x128 tile, 8x8/thread.
__global__ __launch_bounds__(256) void update_kernel(const float* __restrict__ Zin,
                                                     float* __restrict__ Zout) {
    const int b = blockIdx.y;
    const int row0 = blockIdx.x * 128;
    const float* Zb = Zin  + ((size_t)b * NN_ + row0) * DD;
    float*       Ob = Zout + ((size_t)b * NN_ + row0) * DD;
    const float* Mb = g_M + (size_t)b * DD * DD;

    const int tid = threadIdx.x;
    const int tx = tid & 15, ty = tid >> 4;

    __shared__ float As[KT][128], Bs[KT][128];
    float acc[8][8];
#pragma unroll
    for (int u = 0; u < 8; u++)
#pragma unroll
        for (int v = 0; v < 8; v++) acc[u][v] = 0.0f;

    for (int k0 = 0; k0 < DD; k0 += KT) {
#pragma unroll
        for (int t = 0; t < 2; t++) {   // As[kk][n] = Zb[n][k0+kk] (transpose)
            int idx = tid + t * 256;
            int r = idx >> 2, c4 = (idx & 3) * 4;
            float4 v = *(const float4*)&Zb[(size_t)r * DD + k0 + c4];
            As[c4 + 0][r] = v.x; As[c4 + 1][r] = v.y;
            As[c4 + 2][r] = v.z; As[c4 + 3][r] = v.w;
        }
#pragma unroll
        for (int t = 0; t < 2; t++) {   // Bs[kk][i] = M[k0+kk][i] (direct)
            int idx = tid + t * 256;
            int r = idx >> 5, c = (idx & 31) * 4;
            *(float4*)&Bs[r][c] = *(const float4*)&Mb[(size_t)(k0 + r) * DD + c];
        }
        __syncthreads();
#pragma unroll
        for (int k = 0; k < KT; k++) {
            float a[8], bv[8];
            *(float4*)&a[0]  = *(const float4*)&As[k][ty * 8];
            *(float4*)&a[4]  = *(const float4*)&As[k][ty * 8 + 4];
            *(float4*)&bv[0] = *(const float4*)&Bs[k][tx * 8];
            *(float4*)&bv[4] = *(const float4*)&Bs[k][tx * 8 + 4];
#pragma unroll
            for (int u = 0; u < 8; u++)
#pragma unroll
                for (int v = 0; v < 8; v++)
                    acc[u][v] = fmaf(a[u], bv[v], acc[u][v]);
        }
        __syncthreads();
    }

    // Epilogue: out = Zin + acc (read-before-write per address, in-place safe)
#pragma unroll
    for (int u = 0; u < 8; u++) {
        int r = ty * 8 + u;
        float4 z0 = *(const float4*)&Zb[(size_t)r * DD + tx * 8];
        float4 z1 = *(const float4*)&Zb[(size_t)r * DD + tx * 8 + 4];
        float4 o0 = make_float4(z0.x + acc[u][0], z0.y + acc[u][1],
                                z0.z + acc[u][2], z0.w + acc[u][3]);
        float4 o1 = make_float4(z1.x + acc[u][4], z1.y + acc[u][5],
                                z1.z + acc[u][6], z1.w + acc[u][7]);
        *(float4*)&Ob[(size_t)r * DD + tx * 8]     = o0;
        *(float4*)&Ob[(size_t)r * DD + tx * 8 + 4] = o1;
    }
}

// ---------------------------------------------------------------------------
extern "C" void kernel_launch(void* const* d_in, const int* in_sizes, int n_in,
                              void* d_out, int out_size) {
    const float* Z  = (const float*)d_in[0];
    const float* Vm = (const float*)d_in[1];  // [NL, NH, 1, D, D]
    const float* Qm = (const float*)d_in[2];  // [NL, NH, 1, D, D]
    float* out = (float*)d_out;

    for (int l = 0; l < NL; l++) {
        const float* Zin = (l == 0) ? Z : out;
        zero_kernel<<<512, 256>>>();
        gram_kernel<<<dim3(SPLITK, BB), 256>>>(Zin);
        qg_kernel<<<dim3(2, 2, BB * NH), 256>>>(Qm + (size_t)l * NH * DD * DD);
        tv_kernel<<<dim3(2, 2, BB * NH), 256>>>(Vm + (size_t)l * NH * DD * DD);
        update_kernel<<<dim3(NN_ / 128, BB), 256>>>(Zin, out);
    }
}

// round 5
// speedup vs baseline: 2.5517x; 2.5517x over previous
#include <cuda_runtime.h>
#include <cstdint>

// Problem constants
#define BB  8
#define NN_ 2048
#define DD  128
#define NH  8
#define NL  4

// smem tile: 128 rows x 132 floats (stride 132 -> conflict-free fragments)
#define SP 132
#define TILE_F (128 * SP)           // floats
#define TILE_B (TILE_F * 4)         // 67584 bytes

// Ping-pong scratch (layer parity). Flat [2][B*128*128].
__device__ float g_G[2][BB * DD * DD];
__device__ float g_M[2][BB * DD * DD];

// ---------------------------------------------------------------------------
__device__ __forceinline__ uint32_t tf32r(float f) {
    uint32_t u;
    asm("cvt.rna.tf32.f32 %0, %1;" : "=r"(u) : "f"(f));
    return u;
}

// Copy row-major [128x128] fp32 gmem tile -> smem [128][SP], tf32-rounded.
__device__ __forceinline__ void fill_tile(float* S, const float* __restrict__ g, int tid) {
    const float4* s4 = (const float4*)g;
#pragma unroll
    for (int it = 0; it < 16; it++) {
        int i4 = it * 256 + tid;          // 0..4095
        int r = i4 >> 5;
        int c = (i4 & 31) * 4;
        float4 v = s4[i4];
        uint4 o;
        o.x = tf32r(v.x); o.y = tf32r(v.y); o.z = tf32r(v.z); o.w = tf32r(v.w);
        *(uint4*)(S + r * SP + c) = o;
    }
}

// Warp-level 128x128x128 GEMM on mma.sync tf32.
// 8 warps: warpM = wid>>2 (2 x 64 rows), warpN = wid&3 (4 x 32 cols).
// AT: A[m][k] = As[k][m] (transposed smem read). BT: B[k][n] = Bs[n][k].
template<bool AT, bool BT>
__device__ __forceinline__ void warp_gemm(const float* A, const float* B,
                                          float acc[4][4][4], int wid, int lane) {
    const int g = lane >> 2, t = lane & 3;
    const int wm = (wid >> 2) * 64, wn = (wid & 3) * 32;
    const uint32_t* Au = (const uint32_t*)A;
    const uint32_t* Bu = (const uint32_t*)B;
#pragma unroll 4
    for (int ks = 0; ks < 16; ks++) {
        const int k0 = ks * 8;
        uint32_t a[4][4], b[4][2];
#pragma unroll
        for (int mi = 0; mi < 4; mi++) {
            const int m0 = wm + mi * 16;
            if (AT) {
                a[mi][0] = Au[(k0 + t) * SP + m0 + g];
                a[mi][1] = Au[(k0 + t) * SP + m0 + g + 8];
                a[mi][2] = Au[(k0 + t + 4) * SP + m0 + g];
                a[mi][3] = Au[(k0 + t + 4) * SP + m0 + g + 8];
            } else {
                a[mi][0] = Au[(m0 + g) * SP + k0 + t];
                a[mi][1] = Au[(m0 + g + 8) * SP + k0 + t];
                a[mi][2] = Au[(m0 + g) * SP + k0 + t + 4];
                a[mi][3] = Au[(m0 + g + 8) * SP + k0 + t + 4];
            }
        }
#pragma unroll
        for (int ni = 0; ni < 4; ni++) {
            const int n0 = wn + ni * 8;
            if (BT) {
                b[ni][0] = Bu[(n0 + g) * SP + k0 + t];
                b[ni][1] = Bu[(n0 + g) * SP + k0 + t + 4];
            } else {
                b[ni][0] = Bu[(k0 + t) * SP + n0 + g];
                b[ni][1] = Bu[(k0 + t + 4) * SP + n0 + g];
            }
        }
#pragma unroll
        for (int mi = 0; mi < 4; mi++)
#pragma unroll
            for (int ni = 0; ni < 4; ni++)
                asm("mma.sync.aligned.m16n8k8.row.col.f32.tf32.tf32.f32 "
                    "{%0,%1,%2,%3}, {%4,%5,%6,%7}, {%8,%9}, {%0,%1,%2,%3};"
                    : "+f"(acc[mi][ni][0]), "+f"(acc[mi][ni][1]),
                      "+f"(acc[mi][ni][2]), "+f"(acc[mi][ni][3])
                    : "r"(a[mi][0]), "r"(a[mi][1]), "r"(a[mi][2]), "r"(a[mi][3]),
                      "r"(b[ni][0]), "r"(b[ni][1]));
    }
}

#define ZERO_ACC(acc) do { \
    _Pragma("unroll") for (int _i = 0; _i < 4; _i++) \
    _Pragma("unroll") for (int _j = 0; _j < 4; _j++) \
    _Pragma("unroll") for (int _k = 0; _k < 4; _k++) acc[_i][_j][_k] = 0.0f; } while (0)

// ---------------------------------------------------------------------------
// One-time (per call) zero of parity-0 buffers.
__global__ void zero0_kernel() {
    int i = blockIdx.x * blockDim.x + threadIdx.x;   // 512*256 = 131072
    g_G[0][i] = 0.0f;
    g_M[0][i] = 0.0f;
}

// ---------------------------------------------------------------------------
// gram: G[p][b] += Zchunk^T @ Zchunk.  grid (16, B), 256 thr.
__global__ __launch_bounds__(256) void gram_tc(const float* __restrict__ Z, int p) {
    extern __shared__ float smem[];
    const int b = blockIdx.y, s = blockIdx.x;
    const int tid = threadIdx.x, wid = tid >> 5, lane = tid & 31;
    const float* Zb = Z + ((size_t)b * NN_ + (size_t)s * 128) * DD;

    fill_tile(smem, Zb, tid);
    __syncthreads();

    float acc[4][4][4];
    ZERO_ACC(acc);
    warp_gemm<true, false>(smem, smem, acc, wid, lane);   // A = Z^T, B = Z

    float* Gb = g_G[p] + (size_t)b * DD * DD;
    const int g = lane >> 2, t = lane & 3;
    const int wm = (wid >> 2) * 64, wn = (wid & 3) * 32;
#pragma unroll
    for (int mi = 0; mi < 4; mi++)
#pragma unroll
        for (int ni = 0; ni < 4; ni++) {
            const int r = wm + mi * 16 + g, c = wn + ni * 8 + 2 * t;
            atomicAdd(&Gb[(size_t)r * DD + c],           acc[mi][ni][0]);
            atomicAdd(&Gb[(size_t)r * DD + c + 1],       acc[mi][ni][1]);
            atomicAdd(&Gb[(size_t)(r + 8) * DD + c],     acc[mi][ni][2]);
            atomicAdd(&Gb[(size_t)(r + 8) * DD + c + 1], acc[mi][ni][3]);
        }
}

// ---------------------------------------------------------------------------
// qgtv: T = Q_j @ G_b;  M[p][b] += T @ V_j^T / (N*NH).  grid (B*NH), 256 thr.
__global__ __launch_bounds__(256) void qgtv_tc(const float* __restrict__ Qm,
                                               const float* __restrict__ Vm, int p) {
    extern __shared__ float smem[];
    float* bufA = smem;
    float* bufB = smem + TILE_F;
    const int bj = blockIdx.x, b = bj >> 3, j = bj & 7;
    const int tid = threadIdx.x, wid = tid >> 5, lane = tid & 31;
    const int g = lane >> 2, t = lane & 3;
    const int wm = (wid >> 2) * 64, wn = (wid & 3) * 32;

    fill_tile(bufA, Qm + (size_t)j * DD * DD, tid);            // A = Q_j
    fill_tile(bufB, g_G[p] + (size_t)b * DD * DD, tid);        // B = G_b
    __syncthreads();

    float acc[4][4][4];
    ZERO_ACC(acc);
    warp_gemm<false, false>(bufA, bufB, acc, wid, lane);       // T = Q @ G
    __syncthreads();                                           // done reading bufA/bufB

    {   // write T into bufA (tf32), load V into bufB
        uint32_t* Tu = (uint32_t*)bufA;
#pragma unroll
        for (int mi = 0; mi < 4; mi++)
#pragma unroll
            for (int ni = 0; ni < 4; ni++) {
                const int r = wm + mi * 16 + g, c = wn + ni * 8 + 2 * t;
                Tu[r * SP + c]           = tf32r(acc[mi][ni][0]);
                Tu[r * SP + c + 1]       = tf32r(acc[mi][ni][1]);
                Tu[(r + 8) * SP + c]     = tf32r(acc[mi][ni][2]);
                Tu[(r + 8) * SP + c + 1] = tf32r(acc[mi][ni][3]);
            }
        fill_tile(bufB, Vm + (size_t)j * DD * DD, tid);
    }
    __syncthreads();

    ZERO_ACC(acc);
    warp_gemm<false, true>(bufA, bufB, acc, wid, lane);        // M = T @ V^T

    float* Mb = g_M[p] + (size_t)b * DD * DD;
    const float S = 1.0f / ((float)NN_ * (float)NH);
#pragma unroll
    for (int mi = 0; mi < 4; mi++)
#pragma unroll
        for (int ni = 0; ni < 4; ni++) {
            const int r = wm + mi * 16 + g, c = wn + ni * 8 + 2 * t;
            atomicAdd(&Mb[(size_t)r * DD + c],           acc[mi][ni][0] * S);
            atomicAdd(&Mb[(size_t)r * DD + c + 1],       acc[mi][ni][1] * S);
            atomicAdd(&Mb[(size_t)(r + 8) * DD + c],     acc[mi][ni][2] * S);
            atomicAdd(&Mb[(size_t)(r + 8) * DD + c + 1], acc[mi][ni][3] * S);
        }
}

// ---------------------------------------------------------------------------
// update: Zout = Zin + Zin @ M[p][b]  (row-local, in-place safe).
// Also zeroes parity (1-p) G/M buffers for the next layer. grid (16, B).
__global__ __launch_bounds__(256) void update_tc(const float* __restrict__ Zin,
                                                 float* __restrict__ Zout, int p) {
    extern __shared__ float smem[];
    float* Zs = smem;
    float* Ms = smem + TILE_F;
    const int b = blockIdx.y, rc = blockIdx.x;
    const int tid = threadIdx.x, wid = tid >> 5, lane = tid & 31;
    const size_t zoff = ((size_t)b * NN_ + (size_t)rc * 128) * DD;

    fill_tile(Zs, Zin + zoff, tid);
    fill_tile(Ms, g_M[p] + (size_t)b * DD * DD, tid);
    __syncthreads();

    float acc[4][4][4];
    ZERO_ACC(acc);
    warp_gemm<false, false>(Zs, Ms, acc, wid, lane);

    const int g = lane >> 2, t = lane & 3;
    const int wm = (wid >> 2) * 64, wn = (wid & 3) * 32;
#pragma unroll
    for (int mi = 0; mi < 4; mi++)
#pragma unroll
        for (int ni = 0; ni < 4; ni++) {
            const int r = wm + mi * 16 + g, c = wn + ni * 8 + 2 * t;
            const float2 z0 = *(const float2*)&Zin[zoff + (size_t)r * DD + c];
            const float2 z1 = *(const float2*)&Zin[zoff + (size_t)(r + 8) * DD + c];
            float2 o0 = make_float2(z0.x + acc[mi][ni][0], z0.y + acc[mi][ni][1]);
            float2 o1 = make_float2(z1.x + acc[mi][ni][2], z1.y + acc[mi][ni][3]);
            *(float2*)&Zout[zoff + (size_t)r * DD + c]       = o0;
            *(float2*)&Zout[zoff + (size_t)(r + 8) * DD + c] = o1;
        }

    // Zero next layer's buffers (parity 1-p). 128 blocks x 1024 floats each.
    const int q = 1 - p;
    const int base = (b * 16 + rc) * 1024;
#pragma unroll
    for (int i = 0; i < 4; i++) {
        g_G[q][base + i * 256 + tid] = 0.0f;
        g_M[q][base + i * 256 + tid] = 0.0f;
    }
}

// ---------------------------------------------------------------------------
extern "C" void kernel_launch(void* const* d_in, const int* in_sizes, int n_in,
                              void* d_out, int out_size) {
    const float* Z  = (const float*)d_in[0];
    const float* Vm = (const float*)d_in[1];  // [NL, NH, 1, D, D]
    const float* Qm = (const float*)d_in[2];  // [NL, NH, 1, D, D]
    float* out = (float*)d_out;

    cudaFuncSetAttribute(gram_tc,   cudaFuncAttributeMaxDynamicSharedMemorySize, TILE_B);
    cudaFuncSetAttribute(qgtv_tc,   cudaFuncAttributeMaxDynamicSharedMemorySize, 2 * TILE_B);
    cudaFuncSetAttribute(update_tc, cudaFuncAttributeMaxDynamicSharedMemorySize, 2 * TILE_B);

    zero0_kernel<<<512, 256>>>();
    for (int l = 0; l < NL; l++) {
        const float* Zin = (l == 0) ? Z : out;
        const int p = l & 1;
        gram_tc<<<dim3(16, BB), 256, TILE_B>>>(Zin, p);
        qgtv_tc<<<BB * NH, 256, 2 * TILE_B>>>(Qm + (size_t)l * NH * DD * DD,
                                              Vm + (size_t)l * NH * DD * DD, p);
        update_tc<<<dim3(16, BB), 256, 2 * TILE_B>>>(Zin, out, p);
    }
}

// round 6
// speedup vs baseline: 2.6034x; 1.0202x over previous
#include <cuda_runtime.h>
#include <cstdint>

// Problem constants
#define BB  8
#define NN_ 2048
#define DD  128
#define NH  8
#define NL  4

#define SP   132                     // smem row stride (floats)
#define T64F (64 * SP)               // 64-row tile floats  (33792 B)
#define T128F (128 * SP)             // 128-row tile floats (67584 B)
#define SM_QU (4 * (T64F + T128F))   // 101376 B dynamic smem

// Scratch
__device__ float g_Gp[32 * BB * DD * DD];   // gram partials [chunk][b][128*128] (16.7MB)
__device__ float g_G[BB * DD * DD];         // reduced Gram
__device__ float g_M[BB * DD * DD];         // per-batch update matrix

// ---------------------------------------------------------------------------
__device__ __forceinline__ uint32_t tf32r(float f) {
    uint32_t u;
    asm("cvt.rna.tf32.f32 %0, %1;" : "=r"(u) : "f"(f));
    return u;
}

// Copy row-major [NR x 128] fp32 gmem tile -> smem [NR][SP], tf32-rounded. 256 thr.
template<int NR>
__device__ __forceinline__ void fill_tile(float* S, const float* __restrict__ g, int tid) {
    const float4* s4 = (const float4*)g;
#pragma unroll
    for (int it = 0; it < NR / 8; it++) {
        int i4 = it * 256 + tid;
        int r = i4 >> 5;
        int c = (i4 & 31) * 4;
        float4 v = s4[i4];
        uint4 o;
        o.x = tf32r(v.x); o.y = tf32r(v.y); o.z = tf32r(v.z); o.w = tf32r(v.w);
        *(uint4*)(S + r * SP + c) = o;
    }
}

// Warp-level GEMM on mma.sync tf32. Warp tile = (MI*16) x 32 at (wm, wn).
// KS k-steps of 8. AT: A(m,k)=As[k][m]. BT: B(k,n)=Bs[n][k].
template<int MI, int KS, bool AT, bool BT>
__device__ __forceinline__ void wgemm(const float* A, const float* B,
                                      float (&acc)[MI][4][4], int wm, int wn, int lane) {
    const int g = lane >> 2, t = lane & 3;
    const uint32_t* Au = (const uint32_t*)A;
    const uint32_t* Bu = (const uint32_t*)B;
#pragma unroll 4
    for (int ks = 0; ks < KS; ks++) {
        const int k0 = ks * 8;
        uint32_t a[MI][4], b[4][2];
#pragma unroll
        for (int mi = 0; mi < MI; mi++) {
            const int m0 = wm + mi * 16;
            if (AT) {
                a[mi][0] = Au[(k0 + t) * SP + m0 + g];
                a[mi][1] = Au[(k0 + t) * SP + m0 + g + 8];
                a[mi][2] = Au[(k0 + t + 4) * SP + m0 + g];
                a[mi][3] = Au[(k0 + t + 4) * SP + m0 + g + 8];
            } else {
                a[mi][0] = Au[(m0 + g) * SP + k0 + t];
                a[mi][1] = Au[(m0 + g + 8) * SP + k0 + t];
                a[mi][2] = Au[(m0 + g) * SP + k0 + t + 4];
                a[mi][3] = Au[(m0 + g + 8) * SP + k0 + t + 4];
            }
        }
#pragma unroll
        for (int ni = 0; ni < 4; ni++) {
            const int n0 = wn + ni * 8;
            if (BT) {
                b[ni][0] = Bu[(n0 + g) * SP + k0 + t];
                b[ni][1] = Bu[(n0 + g) * SP + k0 + t + 4];
            } else {
                b[ni][0] = Bu[(k0 + t) * SP + n0 + g];
                b[ni][1] = Bu[(k0 + t + 4) * SP + n0 + g];
            }
        }
#pragma unroll
        for (int mi = 0; mi < MI; mi++)
#pragma unroll
            for (int ni = 0; ni < 4; ni++)
                asm("mma.sync.aligned.m16n8k8.row.col.f32.tf32.tf32.f32 "
                    "{%0,%1,%2,%3}, {%4,%5,%6,%7}, {%8,%9}, {%0,%1,%2,%3};"
                    : "+f"(acc[mi][ni][0]), "+f"(acc[mi][ni][1]),
                      "+f"(acc[mi][ni][2]), "+f"(acc[mi][ni][3])
                    : "r"(a[mi][0]), "r"(a[mi][1]), "r"(a[mi][2]), "r"(a[mi][3]),
                      "r"(b[ni][0]), "r"(b[ni][1]));
    }
}

#define ZERO_ACC(acc, MI) do { \
    _Pragma("unroll") for (int _i = 0; _i < (MI); _i++) \
    _Pragma("unroll") for (int _j = 0; _j < 4; _j++) \
    _Pragma("unroll") for (int _k = 0; _k < 4; _k++) acc[_i][_j][_k] = 0.0f; } while (0)

// Store a 128x128 accumulator (8 warps, MI=4) to gmem (plain float2 stores).
__device__ __forceinline__ void store_gram_part(float* P, float (&acc)[4][4][4],
                                                int wm, int wn, int lane) {
    const int g = lane >> 2, t = lane & 3;
#pragma unroll
    for (int mi = 0; mi < 4; mi++)
#pragma unroll
        for (int ni = 0; ni < 4; ni++) {
            const int r = wm + mi * 16 + g, c = wn + ni * 8 + 2 * t;
            *(float2*)&P[(size_t)r * DD + c] =
                make_float2(acc[mi][ni][0], acc[mi][ni][1]);
            *(float2*)&P[(size_t)(r + 8) * DD + c] =
                make_float2(acc[mi][ni][2], acc[mi][ni][3]);
        }
}

// ---------------------------------------------------------------------------
// gram_part: partial Gram of input Z, chunk=64 rows. grid (32, B), 256 thr.
__global__ __launch_bounds__(256, 2) void gram_part(const float* __restrict__ Z) {
    extern __shared__ float smem[];
    const int b = blockIdx.y, s = blockIdx.x;
    const int tid = threadIdx.x, wid = tid >> 5, lane = tid & 31;

    fill_tile<64>(smem, Z + ((size_t)b * NN_ + (size_t)s * 64) * DD, tid);
    __syncthreads();

    float acc[4][4][4];
    ZERO_ACC(acc, 4);
    const int wm = (wid >> 2) * 64, wn = (wid & 3) * 32;
    wgemm<4, 8, true, false>(smem, smem, acc, wm, wn, lane);

    store_gram_part(g_Gp + ((size_t)s * BB + b) * DD * DD, acc, wm, wn, lane);
}

// ---------------------------------------------------------------------------
// greduce: G[b] = sum_s Gp[s][b]; also zeroes M. grid 128, 256 thr (float4).
__global__ __launch_bounds__(256) void greduce() {
    const int idx = blockIdx.x * 256 + threadIdx.x;       // 0..32767 float4 units
    const int b = idx >> 12, i4 = idx & 4095;
    const float4* P = (const float4*)g_Gp;
    float4 s = make_float4(0.f, 0.f, 0.f, 0.f);
#pragma unroll
    for (int c = 0; c < 32; c++) {
        float4 v = P[((size_t)c * BB + b) * 4096 + i4];
        s.x += v.x; s.y += v.y; s.z += v.z; s.w += v.w;
    }
    ((float4*)g_G)[idx] = s;
    ((float4*)g_M)[idx] = make_float4(0.f, 0.f, 0.f, 0.f);
}

// ---------------------------------------------------------------------------
// qgtv: T = Q_j[rows] @ G_b; M[b][rows] += T @ V_j^T / (N*NH). grid (2, B*NH).
__global__ __launch_bounds__(256, 2) void qgtv(const float* __restrict__ Qm,
                                               const float* __restrict__ Vm) {
    extern __shared__ float smem[];
    float* bufA = smem;            // 64 x SP
    float* bufB = smem + T64F;     // 128 x SP
    const int half = blockIdx.x, bj = blockIdx.y, b = bj >> 3, j = bj & 7;
    const int tid = threadIdx.x, wid = tid >> 5, lane = tid & 31;
    const int g = lane >> 2, t = lane & 3;
    const int wm = (wid >> 2) * 32, wn = (wid & 3) * 32;

    fill_tile<64>(bufA, Qm + (size_t)j * DD * DD + (size_t)half * 64 * DD, tid);
    fill_tile<128>(bufB, g_G + (size_t)b * DD * DD, tid);
    __syncthreads();

    float acc[2][4][4];
    ZERO_ACC(acc, 2);
    wgemm<2, 16, false, false>(bufA, bufB, acc, wm, wn, lane);   // T = Q @ G
    __syncthreads();

    {   // T (tf32) into bufA; V into bufB
        uint32_t* Tu = (uint32_t*)bufA;
#pragma unroll
        for (int mi = 0; mi < 2; mi++)
#pragma unroll
            for (int ni = 0; ni < 4; ni++) {
                const int r = wm + mi * 16 + g, c = wn + ni * 8 + 2 * t;
                Tu[r * SP + c]           = tf32r(acc[mi][ni][0]);
                Tu[r * SP + c + 1]       = tf32r(acc[mi][ni][1]);
                Tu[(r + 8) * SP + c]     = tf32r(acc[mi][ni][2]);
                Tu[(r + 8) * SP + c + 1] = tf32r(acc[mi][ni][3]);
            }
        fill_tile<128>(bufB, Vm + (size_t)j * DD * DD, tid);
    }
    __syncthreads();

    ZERO_ACC(acc, 2);
    wgemm<2, 16, false, true>(bufA, bufB, acc, wm, wn, lane);    // M_chunk = T @ V^T

    float* Mb = g_M + (size_t)b * DD * DD;
    const float S = 1.0f / ((float)NN_ * (float)NH);
#pragma unroll
    for (int mi = 0; mi < 2; mi++)
#pragma unroll
        for (int ni = 0; ni < 4; ni++) {
            const int r = half * 64 + wm + mi * 16 + g, c = wn + ni * 8 + 2 * t;
            atomicAdd(&Mb[(size_t)r * DD + c],           acc[mi][ni][0] * S);
            atomicAdd(&Mb[(size_t)r * DD + c + 1],       acc[mi][ni][1] * S);
            atomicAdd(&Mb[(size_t)(r + 8) * DD + c],     acc[mi][ni][2] * S);
            atomicAdd(&Mb[(size_t)(r + 8) * DD + c + 1], acc[mi][ni][3] * S);
        }
}

// ---------------------------------------------------------------------------
// update: Zout = Zin + Zin @ M[b] (64-row chunks, in-place safe), then (fused)
// writes next layer's Gram partial Zout^T @ Zout from smem. grid (32, B).
__global__ __launch_bounds__(256, 2) void update(const float* __restrict__ Zin,
                                                 float* __restrict__ Zout, int do_gram) {
    extern __shared__ float smem[];
    float* bufA = smem;            // 64 x SP  (Zin tile, then Zout tile)
    float* bufB = smem + T64F;     // 128 x SP (M)
    const int b = blockIdx.y, s = blockIdx.x;
    const int tid = threadIdx.x, wid = tid >> 5, lane = tid & 31;
    const int g = lane >> 2, t = lane & 3;
    const size_t zoff = ((size_t)b * NN_ + (size_t)s * 64) * DD;

    fill_tile<64>(bufA, Zin + zoff, tid);
    fill_tile<128>(bufB, g_M + (size_t)b * DD * DD, tid);
    __syncthreads();

    float acc[2][4][4];
    ZERO_ACC(acc, 2);
    const int wm = (wid >> 2) * 32, wn = (wid & 3) * 32;
    wgemm<2, 16, false, false>(bufA, bufB, acc, wm, wn, lane);
    __syncthreads();   // everyone done reading bufA

    // Epilogue: out = Zin + acc; also stash tf32(Zout) in bufA for the gram phase.
    uint32_t* Au = (uint32_t*)bufA;
#pragma unroll
    for (int mi = 0; mi < 2; mi++)
#pragma unroll
        for (int ni = 0; ni < 4; ni++) {
            const int r = wm + mi * 16 + g, c = wn + ni * 8 + 2 * t;
            const float2 z0 = *(const float2*)&Zin[zoff + (size_t)r * DD + c];
            const float2 z1 = *(const float2*)&Zin[zoff + (size_t)(r + 8) * DD + c];
            float2 o0 = make_float2(z0.x + acc[mi][ni][0], z0.y + acc[mi][ni][1]);
            float2 o1 = make_float2(z1.x + acc[mi][ni][2], z1.y + acc[mi][ni][3]);
            *(float2*)&Zout[zoff + (size_t)r * DD + c]       = o0;
            *(float2*)&Zout[zoff + (size_t)(r + 8) * DD + c] = o1;
            Au[r * SP + c]           = tf32r(o0.x);
            Au[r * SP + c + 1]       = tf32r(o0.y);
            Au[(r + 8) * SP + c]     = tf32r(o1.x);
            Au[(r + 8) * SP + c + 1] = tf32r(o1.y);
        }

    if (!do_gram) return;
    __syncthreads();

    // Fused gram partial: Gp[s][b] = Zout_chunk^T @ Zout_chunk (K=64).
    float acc2[4][4][4];
    ZERO_ACC(acc2, 4);
    const int wm2 = (wid >> 2) * 64, wn2 = (wid & 3) * 32;
    wgemm<4, 8, true, false>(bufA, bufA, acc2, wm2, wn2, lane);
    store_gram_part(g_Gp + ((size_t)s * BB + b) * DD * DD, acc2, wm2, wn2, lane);
}

// ---------------------------------------------------------------------------
extern "C" void kernel_launch(void* const* d_in, const int* in_sizes, int n_in,
                              void* d_out, int out_size) {
    const float* Z  = (const float*)d_in[0];
    const float* Vm = (const float*)d_in[1];  // [NL, NH, 1, D, D]
    const float* Qm = (const float*)d_in[2];  // [NL, NH, 1, D, D]
    float* out = (float*)d_out;

    cudaFuncSetAttribute(gram_part, cudaFuncAttributeMaxDynamicSharedMemorySize, T64F * 4);
    cudaFuncSetAttribute(qgtv,      cudaFuncAttributeMaxDynamicSharedMemorySize, SM_QU);
    cudaFuncSetAttribute(update,    cudaFuncAttributeMaxDynamicSharedMemorySize, SM_QU);

    gram_part<<<dim3(32, BB), 256, T64F * 4>>>(Z);
    for (int l = 0; l < NL; l++) {
        const float* Zin = (l == 0) ? Z : out;
        greduce<<<128, 256>>>();
        qgtv<<<dim3(2, BB * NH), 256, SM_QU>>>(Qm + (size_t)l * NH * DD * DD,
                                               Vm + (size_t)l * NH * DD * DD);
        update<<<dim3(32, BB), 256, SM_QU>>>(Zin, out, l < NL - 1);
    }
}

// round 8
// speedup vs baseline: 2.9364x; 1.1279x over previous
#include <cuda_runtime.h>
#include <cstdint>

// Problem constants
#define BB  8
#define NN_ 2048
#define DD  128
#define NH  8
#define NL  4
#define NCHUNK 16                    // gram split-K chunks (128 rows each)

#define SP   140                     // smem row stride: 140 % 32 == 12 -> all 4 fragment
                                     // patterns (12t+g, 12g+t) are bank-conflict-free
#define T64F (64 * SP)
#define T128F (128 * SP)
#define SM_GRAM (T128F * 4)          // 71680 B
#define SM_UPD  (2 * T128F * 4)      // 143360 B
#define SM_QG   ((T64F + T128F) * 4) // 107520 B

// Scratch
__device__ float g_Gp[NCHUNK * BB * DD * DD];  // gram partials (8.4MB)
__device__ float g_G[BB * DD * DD];            // reduced Gram
__device__ float g_M[BB * DD * DD];            // per-batch update matrix

// ---------------------------------------------------------------------------
__device__ __forceinline__ uint32_t tf32r(float f) {
    uint32_t u;
    asm("cvt.rna.tf32.f32 %0, %1;" : "=r"(u) : "f"(f));
    return u;
}

// Copy row-major [NR x 128] fp32 gmem tile -> smem [NR][SP], tf32-rounded.
template<int NR, int NT>
__device__ __forceinline__ void fill_tile(float* S, const float* __restrict__ g, int tid) {
    const float4* s4 = (const float4*)g;
#pragma unroll
    for (int it = 0; it < NR * 32 / NT; it++) {
        int i4 = it * NT + tid;
        int r = i4 >> 5;
        int c = (i4 & 31) * 4;
        float4 v = s4[i4];
        uint4 o;
        o.x = tf32r(v.x); o.y = tf32r(v.y); o.z = tf32r(v.z); o.w = tf32r(v.w);
        *(uint4*)(S + r * SP + c) = o;
    }
}

// Warp-level GEMM on mma.sync tf32. Warp tile = (MI*16) x 32 at (wm, wn).
// KS k-steps of 8. AT: A(m,k)=As[k][m]. BT: B(k,n)=Bs[n][k].
template<int MI, int KS, bool AT, bool BT>
__device__ __forceinline__ void wgemm(const float* A, const float* B,
                                      float (&acc)[MI][4][4], int wm, int wn, int lane) {
    const int g = lane >> 2, t = lane & 3;
    const uint32_t* Au = (const uint32_t*)A;
    const uint32_t* Bu = (const uint32_t*)B;
#pragma unroll 4
    for (int ks = 0; ks < KS; ks++) {
        const int k0 = ks * 8;
        uint32_t a[MI][4], b[4][2];
#pragma unroll
        for (int mi = 0; mi < MI; mi++) {
            const int m0 = wm + mi * 16;
            if (AT) {
                a[mi][0] = Au[(k0 + t) * SP + m0 + g];
                a[mi][1] = Au[(k0 + t) * SP + m0 + g + 8];
                a[mi][2] = Au[(k0 + t + 4) * SP + m0 + g];
                a[mi][3] = Au[(k0 + t + 4) * SP + m0 + g + 8];
            } else {
                a[mi][0] = Au[(m0 + g) * SP + k0 + t];
                a[mi][1] = Au[(m0 + g + 8) * SP + k0 + t];
                a[mi][2] = Au[(m0 + g) * SP + k0 + t + 4];
                a[mi][3] = Au[(m0 + g + 8) * SP + k0 + t + 4];
            }
        }
#pragma unroll
        for (int ni = 0; ni < 4; ni++) {
            const int n0 = wn + ni * 8;
            if (BT) {
                b[ni][0] = Bu[(n0 + g) * SP + k0 + t];
                b[ni][1] = Bu[(n0 + g) * SP + k0 + t + 4];
            } else {
                b[ni][0] = Bu[(k0 + t) * SP + n0 + g];
                b[ni][1] = Bu[(k0 + t + 4) * SP + n0 + g];
            }
        }
#pragma unroll
        for (int mi = 0; mi < MI; mi++)
#pragma unroll
            for (int ni = 0; ni < 4; ni++)
                asm("mma.sync.aligned.m16n8k8.row.col.f32.tf32.tf32.f32 "
                    "{%0,%1,%2,%3}, {%4,%5,%6,%7}, {%8,%9}, {%0,%1,%2,%3};"
                    : "+f"(acc[mi][ni][0]), "+f"(acc[mi][ni][1]),
                      "+f"(acc[mi][ni][2]), "+f"(acc[mi][ni][3])
                    : "r"(a[mi][0]), "r"(a[mi][1]), "r"(a[mi][2]), "r"(a[mi][3]),
                      "r"(b[ni][0]), "r"(b[ni][1]));
    }
}

#define ZERO_ACC(acc, MI) do { \
    _Pragma("unroll") for (int _i = 0; _i < (MI); _i++) \
    _Pragma("unroll") for (int _j = 0; _j < 4; _j++) \
    _Pragma("unroll") for (int _k = 0; _k < 4; _k++) acc[_i][_j][_k] = 0.0f; } while (0)

template<int MI>
__device__ __forceinline__ void store_part(float* P, float (&acc)[MI][4][4],
                                           int wm, int wn, int lane) {
    const int g = lane >> 2, t = lane & 3;
#pragma unroll
    for (int mi = 0; mi < MI; mi++)
#pragma unroll
        for (int ni = 0; ni < 4; ni++) {
            const int r = wm + mi * 16 + g, c = wn + ni * 8 + 2 * t;
            *(float2*)&P[(size_t)r * DD + c] =
                make_float2(acc[mi][ni][0], acc[mi][ni][1]);
            *(float2*)&P[(size_t)(r + 8) * DD + c] =
                make_float2(acc[mi][ni][2], acc[mi][ni][3]);
        }
}

// ---------------------------------------------------------------------------
// gram_part: partial Gram of input Z, chunk=128 rows. grid (16, B), 512 thr.
__global__ __launch_bounds__(512) void gram_part(const float* __restrict__ Z) {
    extern __shared__ float smem[];
    const int b = blockIdx.y, s = blockIdx.x;
    const int tid = threadIdx.x, wid = tid >> 5, lane = tid & 31;

    fill_tile<128, 512>(smem, Z + ((size_t)b * NN_ + (size_t)s * 128) * DD, tid);
    __syncthreads();

    float acc[2][4][4];
    ZERO_ACC(acc, 2);
    const int wm = (wid >> 2) * 32, wn = (wid & 3) * 32;
    wgemm<2, 16, true, false>(smem, smem, acc, wm, wn, lane);

    store_part<2>(g_Gp + ((size_t)s * BB + b) * DD * DD, acc, wm, wn, lane);
}

// ---------------------------------------------------------------------------
// greduce: G[b] = sum_s Gp[s][b]; also zeroes M. grid 128, 256 thr (float4).
__global__ __launch_bounds__(256) void greduce() {
    const int idx = blockIdx.x * 256 + threadIdx.x;       // 0..32767 float4 units
    const int b = idx >> 12, i4 = idx & 4095;
    const float4* P = (const float4*)g_Gp;
    float4 s = make_float4(0.f, 0.f, 0.f, 0.f);
#pragma unroll
    for (int c = 0; c < NCHUNK; c++) {
        float4 v = P[((size_t)c * BB + b) * 4096 + i4];
        s.x += v.x; s.y += v.y; s.z += v.z; s.w += v.w;
    }
    ((float4*)g_G)[idx] = s;
    ((float4*)g_M)[idx] = make_float4(0.f, 0.f, 0.f, 0.f);
}

// ---------------------------------------------------------------------------
// qgtv: T = Q_j[rows] @ G_b; M[b][rows] += T @ V_j^T / (N*NH). grid (2, B*NH), 256 thr.
__global__ __launch_bounds__(256, 2) void qgtv(const float* __restrict__ Qm,
                                               const float* __restrict__ Vm) {
    extern __shared__ float smem[];
    float* bufA = smem;            // 64 x SP
    float* bufB = smem + T64F;     // 128 x SP
    const int half = blockIdx.x, bj = blockIdx.y, b = bj >> 3, j = bj & 7;
    const int tid = threadIdx.x, wid = tid >> 5, lane = tid & 31;
    const int g = lane >> 2, t = lane & 3;
    const int wm = (wid >> 2) * 32, wn = (wid & 3) * 32;

    fill_tile<64, 256>(bufA, Qm + (size_t)j * DD * DD + (size_t)half * 64 * DD, tid);
    fill_tile<128, 256>(bufB, g_G + (size_t)b * DD * DD, tid);
    __syncthreads();

    float acc[2][4][4];
    ZERO_ACC(acc, 2);
    wgemm<2, 16, false, false>(bufA, bufB, acc, wm, wn, lane);   // T = Q @ G
    __syncthreads();

    {   // T (tf32) into bufA; V into bufB
        uint32_t* Tu = (uint32_t*)bufA;
#pragma unroll
        for (int mi = 0; mi < 2; mi++)
#pragma unroll
            for (int ni = 0; ni < 4; ni++) {
                const int r = wm + mi * 16 + g, c = wn + ni * 8 + 2 * t;
                Tu[r * SP + c]           = tf32r(acc[mi][ni][0]);
                Tu[r * SP + c + 1]       = tf32r(acc[mi][ni][1]);
                Tu[(r + 8) * SP + c]     = tf32r(acc[mi][ni][2]);
                Tu[(r + 8) * SP + c + 1] = tf32r(acc[mi][ni][3]);
            }
        fill_tile<128, 256>(bufB, Vm + (size_t)j * DD * DD, tid);
    }
    __syncthreads();

    ZERO_ACC(acc, 2);
    wgemm<2, 16, false, true>(bufA, bufB, acc, wm, wn, lane);    // M_chunk = T @ V^T

    float* Mb = g_M + (size_t)b * DD * DD;
    const float S = 1.0f / ((float)NN_ * (float)NH);
#pragma unroll
    for (int mi = 0; mi < 2; mi++)
#pragma unroll
        for (int ni = 0; ni < 4; ni++) {
            const int r = half * 64 + wm + mi * 16 + g, c = wn + ni * 8 + 2 * t;
            atomicAdd(&Mb[(size_t)r * DD + c],           acc[mi][ni][0] * S);
            atomicAdd(&Mb[(size_t)r * DD + c + 1],       acc[mi][ni][1] * S);
            atomicAdd(&Mb[(size_t)(r + 8) * DD + c],     acc[mi][ni][2] * S);
            atomicAdd(&Mb[(size_t)(r + 8) * DD + c + 1], acc[mi][ni][3] * S);
        }
}

// ---------------------------------------------------------------------------
// update: Zout = Zin + Zin @ M[b] (128-row chunks, in-place safe), then (fused)
// writes next layer's Gram partial Zout^T @ Zout. grid (16, B), 512 thr.
__global__ __launch_bounds__(512) void update(const float* __restrict__ Zin,
                                              float* __restrict__ Zout, int do_gram) {
    extern __shared__ float smem[];
    float* bufA = smem;            // 128 x SP (Zin tile -> Zout tile)
    float* bufB = smem + T128F;    // 128 x SP (M)
    const int b = blockIdx.y, s = blockIdx.x;
    const int tid = threadIdx.x, wid = tid >> 5, lane = tid & 31;
    const int g = lane >> 2, t = lane & 3;
    const size_t zoff = ((size_t)b * NN_ + (size_t)s * 128) * DD;

    fill_tile<128, 512>(bufA, Zin + zoff, tid);
    fill_tile<128, 512>(bufB, g_M + (size_t)b * DD * DD, tid);
    __syncthreads();

    float acc[2][4][4];
    ZERO_ACC(acc, 2);
    const int wm = (wid >> 2) * 32, wn = (wid & 3) * 32;
    wgemm<2, 16, false, false>(bufA, bufB, acc, wm, wn, lane);
    __syncthreads();   // everyone done reading bufA

    // Epilogue: out = Zin + acc; stash tf32(Zout) in bufA for the gram phase.
    uint32_t* Au = (uint32_t*)bufA;
#pragma unroll
    for (int mi = 0; mi < 2; mi++)
#pragma unroll
        for (int ni = 0; ni < 4; ni++) {
            const int r = wm + mi * 16 + g, c = wn + ni * 8 + 2 * t;
            const float2 z0 = *(const float2*)&Zin[zoff + (size_t)r * DD + c];
            const float2 z1 = *(const float2*)&Zin[zoff + (size_t)(r + 8) * DD + c];
            float2 o0 = make_float2(z0.x + acc[mi][ni][0], z0.y + acc[mi][ni][1]);
            float2 o1 = make_float2(z1.x + acc[mi][ni][2], z1.y + acc[mi][ni][3]);
            *(float2*)&Zout[zoff + (size_t)r * DD + c]       = o0;
            *(float2*)&Zout[zoff + (size_t)(r + 8) * DD + c] = o1;
            Au[r * SP + c]           = tf32r(o0.x);
            Au[r * SP + c + 1]       = tf32r(o0.y);
            Au[(r + 8) * SP + c]     = tf32r(o1.x);
            Au[(r + 8) * SP + c + 1] = tf32r(o1.y);
        }

    if (!do_gram) return;
    __syncthreads();

    // Fused gram partial: Gp[s][b] = Zout_chunk^T @ Zout_chunk (K=128).
    float acc2[2][4][4];
    ZERO_ACC(acc2, 2);
    wgemm<2, 16, true, false>(bufA, bufA, acc2, wm, wn, lane);
    store_part<2>(g_Gp + ((size_t)s * BB + b) * DD * DD, acc2, wm, wn, lane);
}

// ---------------------------------------------------------------------------
extern "C" void kernel_launch(void* const* d_in, const int* in_sizes, int n_in,
                              void* d_out, int out_size) {
    const float* Z  = (const float*)d_in[0];
    const float* Vm = (const float*)d_in[1];  // [NL, NH, 1, D, D]
    const float* Qm = (const float*)d_in[2];  // [NL, NH, 1, D, D]
    float* out = (float*)d_out;

    cudaFuncSetAttribute(gram_part, cudaFuncAttributeMaxDynamicSharedMemorySize, SM_GRAM);
    cudaFuncSetAttribute(qgtv,      cudaFuncAttributeMaxDynamicSharedMemorySize, SM_QG);
    cudaFuncSetAttribute(update,    cudaFuncAttributeMaxDynamicSharedMemorySize, SM_UPD);

    gram_part<<<dim3(NCHUNK, BB), 512, SM_GRAM>>>(Z);
    for (int l = 0; l < NL; l++) {
        const float* Zin = (l == 0) ? Z : out;
        greduce<<<128, 256>>>();
        qgtv<<<dim3(2, BB * NH), 256, SM_QG>>>(Qm + (size_t)l * NH * DD * DD,
                                               Vm + (size_t)l * NH * DD * DD);
        update<<<dim3(NCHUNK, BB), 512, SM_UPD>>>(Zin, out, l < NL - 1);
    }
}